// round 2
// baseline (speedup 1.0000x reference)
#include <cuda_runtime.h>

#define NMAX 50000
#define EMAX 800000
#define RS 132  // 128 + 4 pad (132*4B = 16B-aligned row stride)

typedef unsigned long long ull;

// ------------------------- static device scratch ---------------------------
__device__ __align__(16) float  g_px[NMAX * 64];          // x @ w1m_top
__device__ __align__(16) float  g_h[EMAX * 64];           // pre-BN activations (edge, then node)
__device__ __align__(16) float  g_S[NMAX * 64];           // scattered relu sums
__device__ float  g_cnt[NMAX];
__device__ float  g_sum_m[64], g_sq_m[64], g_sum_n[64], g_sq_n[64];
__device__ __align__(16) float g_am[64], g_cm[64], g_an[64], g_cn[64];
__device__ __align__(16) float g_Wc[64 * 64];             // w2m @ w1n_bot
__device__ __align__(16) float g_bvec[64];                // b2m @ w1n_bot

// ------------------------- f32x2 packed FMA helpers ------------------------
__device__ __forceinline__ ull pk2(float x) {
    ull r; asm("mov.b64 %0, {%1, %1};" : "=l"(r) : "f"(x)); return r;
}
__device__ __forceinline__ void fma2(ull& d, ull a, ull b) {
    asm("fma.rn.f32x2 %0, %1, %2, %0;" : "+l"(d) : "l"(a), "l"(b));
}
__device__ __forceinline__ void unpk(ull v, float& lo, float& hi) {
    asm("mov.b64 {%0, %1}, %2;" : "=f"(lo), "=f"(hi) : "l"(v));
}

// ------------------------- GEMM tile core ----------------------------------
// 128 threads, 128 rows x 64 cols tile, K in chunks of 32.
// c = tid&7 (8 col-groups of 8), r = tid>>3 (16 row-groups of 8).
__device__ __forceinline__ void stageT(float* sAT, float4 v, int row, int kq) {
    sAT[(4 * kq + 0) * RS + row] = v.x;
    sAT[(4 * kq + 1) * RS + row] = v.y;
    sAT[(4 * kq + 2) * RS + row] = v.z;
    sAT[(4 * kq + 3) * RS + row] = v.w;
}

__device__ __forceinline__ void mm32(const float* sAT, const float* sW,
                                     int r, int c, ull acc[8][4]) {
#pragma unroll 4
    for (int k = 0; k < 32; ++k) {
        const float4 A0 = *(const float4*)(sAT + k * RS + 8 * r);
        const float4 A1 = *(const float4*)(sAT + k * RS + 8 * r + 4);
        const ulonglong2 Bv0 = *(const ulonglong2*)(sW + k * 64 + 8 * c);
        const ulonglong2 Bv1 = *(const ulonglong2*)(sW + k * 64 + 8 * c + 4);
        float av[8] = {A0.x, A0.y, A0.z, A0.w, A1.x, A1.y, A1.z, A1.w};
#pragma unroll
        for (int i = 0; i < 8; ++i) {
            ull Ad = pk2(av[i]);
            fma2(acc[i][0], Ad, Bv0.x);
            fma2(acc[i][1], Ad, Bv0.y);
            fma2(acc[i][2], Ad, Bv1.x);
            fma2(acc[i][3], Ad, Bv1.y);
        }
    }
}

// ------------------------- k_zero ------------------------------------------
__global__ void k_zero(int N) {
    int i = blockIdx.x * blockDim.x + threadIdx.x;
    if (i < N * 16) ((float4*)g_S)[i] = make_float4(0.f, 0.f, 0.f, 0.f);
    if (i < N) g_cnt[i] = 0.f;
    if (i < 64) { g_sum_m[i] = 0.f; g_sq_m[i] = 0.f; g_sum_n[i] = 0.f; g_sq_n[i] = 0.f; }
}

// ------------------------- k_wc: Wc = w2m @ w1n_bot ------------------------
__global__ void k_wc(const float* __restrict__ w2m, const float* __restrict__ w1n,
                     const float* __restrict__ b2m) {
    __shared__ __align__(16) float sB[64 * 64];
    int tid = threadIdx.x;
    for (int idx = tid; idx < 1024; idx += 256) {
        int k = idx >> 4, cq = idx & 15;
        *(float4*)&sB[k * 64 + cq * 4] = *(const float4*)&w1n[(64 + k) * 64 + cq * 4];
    }
    __syncthreads();
    for (int idx = tid; idx < 4096; idx += 256) {
        int i = idx >> 6, j = idx & 63;
        float s = 0.f;
#pragma unroll 8
        for (int k = 0; k < 64; ++k) s += w2m[i * 64 + k] * sB[k * 64 + j];
        g_Wc[idx] = s;
    }
    if (tid < 64) {
        float s = 0.f;
#pragma unroll 8
        for (int k = 0; k < 64; ++k) s += b2m[k] * sB[k * 64 + tid];
        g_bvec[tid] = s;
    }
}

// ------------------------- k_px: px = x @ w1m_top --------------------------
__global__ __launch_bounds__(128) void k_px(const float* __restrict__ x,
                                            const float* __restrict__ w1m, int N) {
    __shared__ __align__(16) float sAT[32 * RS];
    __shared__ __align__(16) float sW[64 * 64];
    const int tid = threadIdx.x, c = tid & 7, r = tid >> 3;
    const int n0 = blockIdx.x * 128;

    for (int idx = tid; idx < 1024; idx += 128) {
        int k = idx >> 4, cq = idx & 15;
        *(float4*)&sW[k * 64 + cq * 4] = *(const float4*)&w1m[k * 64 + cq * 4];
    }
    ull acc[8][4];
#pragma unroll
    for (int i = 0; i < 8; ++i) { acc[i][0] = 0; acc[i][1] = 0; acc[i][2] = 0; acc[i][3] = 0; }

    for (int half = 0; half < 2; ++half) {
        __syncthreads();
#pragma unroll
        for (int it = 0; it < 8; ++it) {
            int idx = tid + it * 128, row = idx >> 3, kq = idx & 7, n = n0 + row;
            float4 v = make_float4(0.f, 0.f, 0.f, 0.f);
            if (n < N) v = *(const float4*)&x[n * 64 + half * 32 + kq * 4];
            stageT(sAT, v, row, kq);
        }
        __syncthreads();
        mm32(sAT, sW + half * 2048, r, c, acc);
    }
#pragma unroll
    for (int i = 0; i < 8; ++i) {
        int n = n0 + 8 * r + i;
        if (n < N) {
            float h[8];
            unpk(acc[i][0], h[0], h[1]); unpk(acc[i][1], h[2], h[3]);
            unpk(acc[i][2], h[4], h[5]); unpk(acc[i][3], h[6], h[7]);
            *(float4*)&g_px[n * 64 + 8 * c]     = make_float4(h[0], h[1], h[2], h[3]);
            *(float4*)&g_px[n * 64 + 8 * c + 4] = make_float4(h[4], h[5], h[6], h[7]);
        }
    }
}

// ---- k_edge1: h = px[send] + ea @ w1m_bot + b1m; store h; BN stats --------
__global__ __launch_bounds__(128) void k_edge1(const float* __restrict__ ea,
                                               const int* __restrict__ ei,
                                               const float* __restrict__ w1m,
                                               const float* __restrict__ b1m, int E) {
    __shared__ __align__(16) float sAT[32 * RS];
    __shared__ __align__(16) float sW[64 * 64];
    __shared__ int   sSend[128];
    __shared__ float sSum[64], sSq[64];
    const int tid = threadIdx.x, c = tid & 7, r = tid >> 3;
    const int e0 = blockIdx.x * 128;

    for (int idx = tid; idx < 1024; idx += 128) {
        int k = idx >> 4, cq = idx & 15;
        *(float4*)&sW[k * 64 + cq * 4] = *(const float4*)&w1m[4096 + k * 64 + cq * 4];
    }
    { int e = e0 + tid; sSend[tid] = (e < E) ? ei[e] : 0; }
    if (tid < 64) { sSum[tid] = 0.f; sSq[tid] = 0.f; }

    ull acc[8][4];
#pragma unroll
    for (int i = 0; i < 8; ++i) { acc[i][0] = 0; acc[i][1] = 0; acc[i][2] = 0; acc[i][3] = 0; }

    for (int half = 0; half < 2; ++half) {
        __syncthreads();
#pragma unroll
        for (int it = 0; it < 8; ++it) {
            int idx = tid + it * 128, row = idx >> 3, kq = idx & 7, e = e0 + row;
            float4 v = make_float4(0.f, 0.f, 0.f, 0.f);
            if (e < E) v = *(const float4*)&ea[e * 64 + half * 32 + kq * 4];
            stageT(sAT, v, row, kq);
        }
        __syncthreads();
        mm32(sAT, sW + half * 2048, r, c, acc);
    }

    const float4 bb0 = *(const float4*)&b1m[8 * c];
    const float4 bb1 = *(const float4*)&b1m[8 * c + 4];
    float ls[8], lq[8];
#pragma unroll
    for (int j = 0; j < 8; ++j) { ls[j] = 0.f; lq[j] = 0.f; }

#pragma unroll
    for (int i = 0; i < 8; ++i) {
        int row = 8 * r + i, e = e0 + row;
        if (e < E) {
            int snd = sSend[row];
            float4 p0 = *(const float4*)&g_px[snd * 64 + 8 * c];
            float4 p1 = *(const float4*)&g_px[snd * 64 + 8 * c + 4];
            float h[8];
            unpk(acc[i][0], h[0], h[1]); unpk(acc[i][1], h[2], h[3]);
            unpk(acc[i][2], h[4], h[5]); unpk(acc[i][3], h[6], h[7]);
            h[0] += p0.x + bb0.x; h[1] += p0.y + bb0.y;
            h[2] += p0.z + bb0.z; h[3] += p0.w + bb0.w;
            h[4] += p1.x + bb1.x; h[5] += p1.y + bb1.y;
            h[6] += p1.z + bb1.z; h[7] += p1.w + bb1.w;
            *(float4*)&g_h[e * 64 + 8 * c]     = make_float4(h[0], h[1], h[2], h[3]);
            *(float4*)&g_h[e * 64 + 8 * c + 4] = make_float4(h[4], h[5], h[6], h[7]);
#pragma unroll
            for (int j = 0; j < 8; ++j) { ls[j] += h[j]; lq[j] += h[j] * h[j]; }
        }
    }
#pragma unroll
    for (int j = 0; j < 8; ++j) {
        atomicAdd(&sSum[8 * c + j], ls[j]);
        atomicAdd(&sSq[8 * c + j], lq[j]);
    }
    __syncthreads();
    if (tid < 64) {
        atomicAdd(&g_sum_m[tid], sSum[tid]);
        atomicAdd(&g_sq_m[tid], sSq[tid]);
    }
}

// ------------------------- BN coefficient kernels --------------------------
__global__ void k_bnm(const float* __restrict__ gamma, const float* __restrict__ beta,
                      float inv) {
    int j = threadIdx.x;
    float mu = g_sum_m[j] * inv;
    float var = g_sq_m[j] * inv - mu * mu;
    float a = gamma[j] * rsqrtf(var + 1e-5f);
    g_am[j] = a; g_cm[j] = beta[j] - mu * a;
}
__global__ void k_bnn(const float* __restrict__ gamma, const float* __restrict__ beta,
                      float inv) {
    int j = threadIdx.x;
    float mu = g_sum_n[j] * inv;
    float var = g_sq_n[j] * inv - mu * mu;
    float a = gamma[j] * rsqrtf(var + 1e-5f);
    g_an[j] = a; g_cn[j] = beta[j] - mu * a;
}

// ---- k_edge2: relu(bn(h)) scatter-add into g_S, count into g_cnt ----------
__global__ __launch_bounds__(256) void k_edge2(const int* __restrict__ ei, int E) {
    int idx = blockIdx.x * 256 + threadIdx.x;
    if (idx >= E * 16) return;
    int e = idx >> 4, q = idx & 15;
    float4 h = *(const float4*)&g_h[e * 64 + q * 4];
    float4 a = *(const float4*)&g_am[q * 4];
    float4 c = *(const float4*)&g_cm[q * 4];
    float v0 = fmaxf(fmaf(a.x, h.x, c.x), 0.f);
    float v1 = fmaxf(fmaf(a.y, h.y, c.y), 0.f);
    float v2 = fmaxf(fmaf(a.z, h.z, c.z), 0.f);
    float v3 = fmaxf(fmaf(a.w, h.w, c.w), 0.f);
    int rec = ei[E + e];
    float* dst = &g_S[rec * 64 + q * 4];
    asm volatile("red.global.add.v4.f32 [%0], {%1,%2,%3,%4};"
                 :: "l"(dst), "f"(v0), "f"(v1), "f"(v2), "f"(v3) : "memory");
    if (q == 0) atomicAdd(&g_cnt[rec], 1.f);
}

// ---- k_node1: h_n = x@w1n_top + (S/cnt')@Wc + b1n + [cnt>0]*bvec ----------
__global__ __launch_bounds__(128) void k_node1(const float* __restrict__ x,
                                               const float* __restrict__ w1n,
                                               const float* __restrict__ b1n, int N) {
    __shared__ __align__(16) float sAT[32 * RS];
    __shared__ __align__(16) float sW[64 * 64];
    __shared__ float sSum[64], sSq[64];
    const int tid = threadIdx.x, c = tid & 7, r = tid >> 3;
    const int n0 = blockIdx.x * 128;
    if (tid < 64) { sSum[tid] = 0.f; sSq[tid] = 0.f; }

    ull acc[8][4];
#pragma unroll
    for (int i = 0; i < 8; ++i) { acc[i][0] = 0; acc[i][1] = 0; acc[i][2] = 0; acc[i][3] = 0; }

    for (int ph = 0; ph < 2; ++ph) {
        __syncthreads();
        for (int idx = tid; idx < 1024; idx += 128) {
            int k = idx >> 4, cq = idx & 15;
            *(float4*)&sW[k * 64 + cq * 4] = (ph == 0)
                ? *(const float4*)&w1n[k * 64 + cq * 4]
                : *(const float4*)&g_Wc[k * 64 + cq * 4];
        }
        for (int half = 0; half < 2; ++half) {
            __syncthreads();
#pragma unroll
            for (int it = 0; it < 8; ++it) {
                int idx = tid + it * 128, row = idx >> 3, kq = idx & 7, n = n0 + row;
                float4 v = make_float4(0.f, 0.f, 0.f, 0.f);
                if (n < N) {
                    if (ph == 0) {
                        v = *(const float4*)&x[n * 64 + half * 32 + kq * 4];
                    } else {
                        v = *(const float4*)&g_S[n * 64 + half * 32 + kq * 4];
                        float inv = 1.f / fmaxf(g_cnt[n], 1.f);
                        v.x *= inv; v.y *= inv; v.z *= inv; v.w *= inv;
                    }
                }
                stageT(sAT, v, row, kq);
            }
            __syncthreads();
            mm32(sAT, sW + half * 2048, r, c, acc);
        }
    }

    const float4 bb0 = *(const float4*)&b1n[8 * c];
    const float4 bb1 = *(const float4*)&b1n[8 * c + 4];
    const float4 bv0 = *(const float4*)&g_bvec[8 * c];
    const float4 bv1 = *(const float4*)&g_bvec[8 * c + 4];
    float ls[8], lq[8];
#pragma unroll
    for (int j = 0; j < 8; ++j) { ls[j] = 0.f; lq[j] = 0.f; }

#pragma unroll
    for (int i = 0; i < 8; ++i) {
        int n = n0 + 8 * r + i;
        if (n < N) {
            float ind = (g_cnt[n] > 0.f) ? 1.f : 0.f;
            float h[8];
            unpk(acc[i][0], h[0], h[1]); unpk(acc[i][1], h[2], h[3]);
            unpk(acc[i][2], h[4], h[5]); unpk(acc[i][3], h[6], h[7]);
            h[0] += bb0.x + ind * bv0.x; h[1] += bb0.y + ind * bv0.y;
            h[2] += bb0.z + ind * bv0.z; h[3] += bb0.w + ind * bv0.w;
            h[4] += bb1.x + ind * bv1.x; h[5] += bb1.y + ind * bv1.y;
            h[6] += bb1.z + ind * bv1.z; h[7] += bb1.w + ind * bv1.w;
            *(float4*)&g_h[n * 64 + 8 * c]     = make_float4(h[0], h[1], h[2], h[3]);
            *(float4*)&g_h[n * 64 + 8 * c + 4] = make_float4(h[4], h[5], h[6], h[7]);
#pragma unroll
            for (int j = 0; j < 8; ++j) { ls[j] += h[j]; lq[j] += h[j] * h[j]; }
        }
    }
#pragma unroll
    for (int j = 0; j < 8; ++j) {
        atomicAdd(&sSum[8 * c + j], ls[j]);
        atomicAdd(&sSq[8 * c + j], lq[j]);
    }
    __syncthreads();
    if (tid < 64) {
        atomicAdd(&g_sum_n[tid], sSum[tid]);
        atomicAdd(&g_sq_n[tid], sSq[tid]);
    }
}

// ---- k_node2: out = relu(bn(h_n)) @ w2n + b2n -----------------------------
__global__ __launch_bounds__(128) void k_node2(const float* __restrict__ w2n,
                                               const float* __restrict__ b2n,
                                               float* __restrict__ out, int N) {
    __shared__ __align__(16) float sAT[32 * RS];
    __shared__ __align__(16) float sW[64 * 64];
    const int tid = threadIdx.x, c = tid & 7, r = tid >> 3;
    const int n0 = blockIdx.x * 128;

    for (int idx = tid; idx < 1024; idx += 128) {
        int k = idx >> 4, cq = idx & 15;
        *(float4*)&sW[k * 64 + cq * 4] = *(const float4*)&w2n[k * 64 + cq * 4];
    }
    ull acc[8][4];
#pragma unroll
    for (int i = 0; i < 8; ++i) { acc[i][0] = 0; acc[i][1] = 0; acc[i][2] = 0; acc[i][3] = 0; }

    for (int half = 0; half < 2; ++half) {
        __syncthreads();
#pragma unroll
        for (int it = 0; it < 8; ++it) {
            int idx = tid + it * 128, row = idx >> 3, kq = idx & 7, n = n0 + row;
            float4 v = make_float4(0.f, 0.f, 0.f, 0.f);
            if (n < N) {
                int kb = half * 32 + kq * 4;
                float4 h = *(const float4*)&g_h[n * 64 + kb];
                float4 a = *(const float4*)&g_an[kb];
                float4 cc = *(const float4*)&g_cn[kb];
                v.x = fmaxf(fmaf(a.x, h.x, cc.x), 0.f);
                v.y = fmaxf(fmaf(a.y, h.y, cc.y), 0.f);
                v.z = fmaxf(fmaf(a.z, h.z, cc.z), 0.f);
                v.w = fmaxf(fmaf(a.w, h.w, cc.w), 0.f);
            }
            stageT(sAT, v, row, kq);
        }
        __syncthreads();
        mm32(sAT, sW + half * 2048, r, c, acc);
    }
    const float4 bb0 = *(const float4*)&b2n[8 * c];
    const float4 bb1 = *(const float4*)&b2n[8 * c + 4];
#pragma unroll
    for (int i = 0; i < 8; ++i) {
        int n = n0 + 8 * r + i;
        if (n < N) {
            float h[8];
            unpk(acc[i][0], h[0], h[1]); unpk(acc[i][1], h[2], h[3]);
            unpk(acc[i][2], h[4], h[5]); unpk(acc[i][3], h[6], h[7]);
            *(float4*)&out[n * 64 + 8 * c] =
                make_float4(h[0] + bb0.x, h[1] + bb0.y, h[2] + bb0.z, h[3] + bb0.w);
            *(float4*)&out[n * 64 + 8 * c + 4] =
                make_float4(h[4] + bb1.x, h[5] + bb1.y, h[6] + bb1.z, h[7] + bb1.w);
        }
    }
}

// ------------------------- launch ------------------------------------------
extern "C" void kernel_launch(void* const* d_in, const int* in_sizes, int n_in,
                              void* d_out, int out_size) {
    const float* x       = (const float*)d_in[0];
    const int*   ei      = (const int*)d_in[1];
    const float* ea      = (const float*)d_in[2];
    // d_in[3] = u, d_in[4] = batch (unused)
    const float* w1m     = (const float*)d_in[5];
    const float* b1m     = (const float*)d_in[6];
    const float* gamma_m = (const float*)d_in[7];
    const float* beta_m  = (const float*)d_in[8];
    const float* w2m     = (const float*)d_in[9];
    const float* b2m     = (const float*)d_in[10];
    const float* w1n     = (const float*)d_in[11];
    const float* b1n     = (const float*)d_in[12];
    const float* gamma_n = (const float*)d_in[13];
    const float* beta_n  = (const float*)d_in[14];
    const float* w2n     = (const float*)d_in[15];
    const float* b2n     = (const float*)d_in[16];
    float* out = (float*)d_out;

    const int N = in_sizes[0] / 64;
    const int E = in_sizes[2] / 64;
    const int nb = (N + 127) / 128;
    const int eb = (E + 127) / 128;

    k_zero<<<(N * 16 + 255) / 256, 256>>>(N);
    k_wc<<<1, 256>>>(w2m, w1n, b2m);
    k_px<<<nb, 128>>>(x, w1m, N);
    k_edge1<<<eb, 128>>>(ea, ei, w1m, b1m, E);
    k_bnm<<<1, 64>>>(gamma_m, beta_m, 1.f / (float)E);
    k_edge2<<<(E * 16 + 255) / 256, 256>>>(ei, E);
    k_node1<<<nb, 128>>>(x, w1n, b1n, N);
    k_bnn<<<1, 64>>>(gamma_n, beta_n, 1.f / (float)N);
    k_node2<<<nb, 128>>>(w2n, b2n, out, N);
}

// round 4
// speedup vs baseline: 1.0839x; 1.0839x over previous
#include <cuda_runtime.h>
#include <cuda_bf16.h>
#include <cstdint>

#define NMAX 50000
#define RS 132  // FFMA2 tile row stride (128 + 4 pad)

typedef unsigned long long ull;

// ------------------------- static device scratch ---------------------------
__device__ __align__(16) float  g_px[NMAX * 64];          // x @ w1m_top
__device__ __align__(16) float  g_hn[NMAX * 64];          // node pre-BN activations
__device__ __align__(16) float  g_S[NMAX * 64];           // scattered relu sums
__device__ float  g_cnt[NMAX];
__device__ float  g_sum_m[64], g_sq_m[64], g_sum_n[64], g_sq_n[64];
__device__ __align__(16) float g_am[64], g_cm[64], g_an[64], g_cn[64];
__device__ __align__(16) float g_Wc[64 * 64];             // w2m @ w1n_bot
__device__ __align__(16) float g_bvec[64];                // b2m @ w1n_bot

// ------------------------- f32x2 packed FMA helpers ------------------------
__device__ __forceinline__ ull pk2(float x) {
    ull r; asm("mov.b64 %0, {%1, %1};" : "=l"(r) : "f"(x)); return r;
}
__device__ __forceinline__ void fma2(ull& d, ull a, ull b) {
    asm("fma.rn.f32x2 %0, %1, %2, %0;" : "+l"(d) : "l"(a), "l"(b));
}
__device__ __forceinline__ void unpk(ull v, float& lo, float& hi) {
    asm("mov.b64 {%0, %1}, %2;" : "=f"(lo), "=f"(hi) : "l"(v));
}

// ------------------------- mma.sync helpers (plain sm_103-safe) ------------
__device__ __forceinline__ uint32_t smem_u32(const void* p) {
    uint32_t a;
    asm("{ .reg .u64 t; cvta.to.shared.u64 t, %1; cvt.u32.u64 %0, t; }"
        : "=r"(a) : "l"(p));
    return a;
}
// pack (lo, hi) floats into bf16x2 (lo in low half)
__device__ __forceinline__ uint32_t pack_bf2(float lo, float hi) {
    uint32_t r;
    asm("cvt.rn.bf16x2.f32 %0, %1, %2;" : "=r"(r) : "f"(hi), "f"(lo));
    return r;
}

#define LDSM4(R, ADDR) \
    asm volatile("ldmatrix.sync.aligned.m8n8.x4.shared.b16 {%0,%1,%2,%3}, [%4];" \
        : "=r"((R)[0]), "=r"((R)[1]), "=r"((R)[2]), "=r"((R)[3]) : "r"(ADDR))

#define MMA_BF16(D, A, B0, B1) \
    asm volatile("mma.sync.aligned.m16n8k16.row.col.f32.bf16.bf16.f32 " \
        "{%0,%1,%2,%3}, {%4,%5,%6,%7}, {%8,%9}, {%0,%1,%2,%3};" \
        : "+f"((D)[0]), "+f"((D)[1]), "+f"((D)[2]), "+f"((D)[3]) \
        : "r"((A)[0]), "r"((A)[1]), "r"((A)[2]), "r"((A)[3]), "r"(B0), "r"(B1))

// split float4 into bf16x2 hi / lo packs (elements pairwise)
__device__ __forceinline__ void split4(float4 v, uint2& hi, uint2& lo) {
    uint32_t h01 = pack_bf2(v.x, v.y), h23 = pack_bf2(v.z, v.w);
    float r0 = v.x - __uint_as_float(h01 << 16);
    float r1 = v.y - __uint_as_float(h01 & 0xffff0000u);
    float r2 = v.z - __uint_as_float(h23 << 16);
    float r3 = v.w - __uint_as_float(h23 & 0xffff0000u);
    hi = make_uint2(h01, h23);
    lo = make_uint2(pack_bf2(r0, r1), pack_bf2(r2, r3));
}

// smem layout for k_edge (dynamic).  bf16 row stride = 72 elems = 144 B.
#define OFF_BH   0        // 64 x 72 bf16  = 9216
#define OFF_BL   9216     // 9216
#define OFF_SEND 18432    // int[256]
#define OFF_REC  19456    // int[256]
#define OFF_RED  20480    // float[128]
#define OFF_AH   21504    // 256 x 72 bf16 = 36864
#define OFF_AL   58368    // 36864  (ends 95232)
#define OFF_HS   21504    // reused: 256 x 68 f32 = 69632 (ends 91136)
#define SMEM_E   95232

// ------------------------- FFMA2 GEMM tile core (node kernels) -------------
__device__ __forceinline__ void stageT(float* sAT, float4 v, int row, int kq) {
    sAT[(4 * kq + 0) * RS + row] = v.x;
    sAT[(4 * kq + 1) * RS + row] = v.y;
    sAT[(4 * kq + 2) * RS + row] = v.z;
    sAT[(4 * kq + 3) * RS + row] = v.w;
}
__device__ __forceinline__ void mm32(const float* sAT, const float* sW,
                                     int r, int c, ull acc[8][4]) {
#pragma unroll 4
    for (int k = 0; k < 32; ++k) {
        const float4 A0 = *(const float4*)(sAT + k * RS + 8 * r);
        const float4 A1 = *(const float4*)(sAT + k * RS + 8 * r + 4);
        const ulonglong2 Bv0 = *(const ulonglong2*)(sW + k * 64 + 8 * c);
        const ulonglong2 Bv1 = *(const ulonglong2*)(sW + k * 64 + 8 * c + 4);
        float av[8] = {A0.x, A0.y, A0.z, A0.w, A1.x, A1.y, A1.z, A1.w};
#pragma unroll
        for (int i = 0; i < 8; ++i) {
            ull Ad = pk2(av[i]);
            fma2(acc[i][0], Ad, Bv0.x);
            fma2(acc[i][1], Ad, Bv0.y);
            fma2(acc[i][2], Ad, Bv1.x);
            fma2(acc[i][3], Ad, Bv1.y);
        }
    }
}

// ------------------------- k_zero ------------------------------------------
__global__ void k_zero(int N) {
    int i = blockIdx.x * blockDim.x + threadIdx.x;
    if (i < N * 16) ((float4*)g_S)[i] = make_float4(0.f, 0.f, 0.f, 0.f);
    if (i < N) g_cnt[i] = 0.f;
    if (i < 64) { g_sum_m[i] = 0.f; g_sq_m[i] = 0.f; g_sum_n[i] = 0.f; g_sq_n[i] = 0.f; }
}

// ------------------------- k_wc: Wc = w2m @ w1n_bot ------------------------
__global__ void k_wc(const float* __restrict__ w2m, const float* __restrict__ w1n,
                     const float* __restrict__ b2m) {
    __shared__ __align__(16) float sB[64 * 64];
    int tid = threadIdx.x;
    for (int idx = tid; idx < 1024; idx += 256) {
        int k = idx >> 4, cq = idx & 15;
        *(float4*)&sB[k * 64 + cq * 4] = *(const float4*)&w1n[(64 + k) * 64 + cq * 4];
    }
    __syncthreads();
    for (int idx = tid; idx < 4096; idx += 256) {
        int i = idx >> 6, j = idx & 63;
        float s = 0.f;
#pragma unroll 8
        for (int k = 0; k < 64; ++k) s += w2m[i * 64 + k] * sB[k * 64 + j];
        g_Wc[idx] = s;
    }
    if (tid < 64) {
        float s = 0.f;
#pragma unroll 8
        for (int k = 0; k < 64; ++k) s += b2m[k] * sB[k * 64 + tid];
        g_bvec[tid] = s;
    }
}

// ------------------------- k_px: px = x @ w1m_top --------------------------
__global__ __launch_bounds__(128) void k_px(const float* __restrict__ x,
                                            const float* __restrict__ w1m, int N) {
    __shared__ __align__(16) float sAT[32 * RS];
    __shared__ __align__(16) float sW[64 * 64];
    const int tid = threadIdx.x, c = tid & 7, r = tid >> 3;
    const int n0 = blockIdx.x * 128;

    for (int idx = tid; idx < 1024; idx += 128) {
        int k = idx >> 4, cq = idx & 15;
        *(float4*)&sW[k * 64 + cq * 4] = *(const float4*)&w1m[k * 64 + cq * 4];
    }
    ull acc[8][4];
#pragma unroll
    for (int i = 0; i < 8; ++i) { acc[i][0] = 0; acc[i][1] = 0; acc[i][2] = 0; acc[i][3] = 0; }

    for (int half = 0; half < 2; ++half) {
        __syncthreads();
#pragma unroll
        for (int it = 0; it < 8; ++it) {
            int idx = tid + it * 128, row = idx >> 3, kq = idx & 7, n = n0 + row;
            float4 v = make_float4(0.f, 0.f, 0.f, 0.f);
            if (n < N) v = *(const float4*)&x[n * 64 + half * 32 + kq * 4];
            stageT(sAT, v, row, kq);
        }
        __syncthreads();
        mm32(sAT, sW + half * 2048, r, c, acc);
    }
#pragma unroll
    for (int i = 0; i < 8; ++i) {
        int n = n0 + 8 * r + i;
        if (n < N) {
            float h[8];
            unpk(acc[i][0], h[0], h[1]); unpk(acc[i][1], h[2], h[3]);
            unpk(acc[i][2], h[4], h[5]); unpk(acc[i][3], h[6], h[7]);
            *(float4*)&g_px[n * 64 + 8 * c]     = make_float4(h[0], h[1], h[2], h[3]);
            *(float4*)&g_px[n * 64 + 8 * c + 4] = make_float4(h[4], h[5], h[6], h[7]);
        }
    }
}

// ---- k_edge<MODE>: HMMA bf16 3-term GEMM, 256-edge tiles, persistent ------
// MODE 0: accumulate BN column stats only.  MODE 1: BN+ReLU+scatter.
template <int MODE>
__global__ __launch_bounds__(256, 2) void k_edge(const float* __restrict__ ea,
                                                 const int* __restrict__ ei,
                                                 const float* __restrict__ w1m,
                                                 const float* __restrict__ b1m,
                                                 int E, int ntiles) {
    extern __shared__ __align__(1024) char smem[];
    const uint32_t sb = smem_u32(smem);
    const int tid = threadIdx.x, wid = tid >> 5, lane = tid & 31;
    int* sSend = (int*)(smem + OFF_SEND);
    int* sRec  = (int*)(smem + OFF_REC);
    float* sRed = (float*)(smem + OFF_RED);
    float* hs   = (float*)(smem + OFF_HS);

    // stage B (hi/lo split, [n][k] row-major, stride 72 bf16) — once
    for (int idx = tid; idx < 1024; idx += 256) {
        int n = idx & 63, k4 = (idx >> 6) * 4;
        float4 v = make_float4(w1m[4096 + (k4 + 0) * 64 + n],
                               w1m[4096 + (k4 + 1) * 64 + n],
                               w1m[4096 + (k4 + 2) * 64 + n],
                               w1m[4096 + (k4 + 3) * 64 + n]);
        uint2 hi, lo; split4(v, hi, lo);
        *(uint2*)(smem + OFF_BH + n * 144 + k4 * 2) = hi;
        *(uint2*)(smem + OFF_BL + n * 144 + k4 * 2) = lo;
    }
    if (MODE == 0 && tid < 128) sRed[tid] = 0.f;

    const int q = tid & 15;
    const float4 bq = __ldg((const float4*)b1m + q);
    float4 aq, cq;
    if (MODE == 1) { aq = *(const float4*)&g_am[q * 4]; cq = *(const float4*)&g_cm[q * 4]; }
    float4 s = make_float4(0.f, 0.f, 0.f, 0.f);
    float4 s2 = make_float4(0.f, 0.f, 0.f, 0.f);

    // fragment address components
    const int r8 = lane & 7, sel = lane >> 3;
    const uint32_t aBase = sb + (uint32_t)((wid * 32 + r8 + (sel & 1) * 8) * 144
                                           + ((sel >> 1) * 8) * 2);
    const uint32_t bBase = sb + (uint32_t)((((sel >> 1) * 8) + r8) * 144
                                           + ((sel & 1) * 8) * 2);
    const int row0 = lane >> 2, c0 = (lane & 3) * 2;

    for (int t = blockIdx.x; t < ntiles; t += gridDim.x) {
        const int e0 = t * 256;
        __syncthreads();  // protect smem reuse across tiles
        {
            int e = e0 + tid;
            sSend[tid] = (e < E) ? ei[e] : 0;
            if (MODE == 1) sRec[tid] = (e < E) ? ei[E + e] : 0;
        }
        // stage A (hi/lo split)
#pragma unroll
        for (int it = 0; it < 16; ++it) {
            int idx = tid + it * 256, row = idx >> 4, kq = idx & 15;
            float4 v = make_float4(0.f, 0.f, 0.f, 0.f);
            if (e0 + row < E) v = *(const float4*)&ea[(size_t)(e0 + row) * 64 + kq * 4];
            uint2 hi, lo; split4(v, hi, lo);
            uint32_t off = (uint32_t)(row * 144 + kq * 8);
            *(uint2*)(smem + OFF_AH + off) = hi;
            *(uint2*)(smem + OFF_AL + off) = lo;
        }
        __syncthreads();

        // MMA: D = Ah*Bh + Ah*Bl + Al*Bh
        float acc[2][8][4];
#pragma unroll
        for (int mt = 0; mt < 2; ++mt)
#pragma unroll
            for (int nt = 0; nt < 8; ++nt)
#pragma unroll
                for (int j = 0; j < 4; ++j) acc[mt][nt][j] = 0.f;

#pragma unroll
        for (int kt = 0; kt < 4; ++kt) {
            uint32_t aH[2][4], aL[2][4];
#pragma unroll
            for (int mt = 0; mt < 2; ++mt) {
                uint32_t ad = aBase + OFF_AH + mt * 2304 + kt * 32;
                LDSM4(aH[mt], ad);
                LDSM4(aL[mt], ad + (OFF_AL - OFF_AH));
            }
#pragma unroll
            for (int nt2 = 0; nt2 < 4; ++nt2) {
                uint32_t bH[4], bL[4];
                uint32_t bd = bBase + OFF_BH + nt2 * 2304 + kt * 32;
                LDSM4(bH, bd);
                LDSM4(bL, bd + (OFF_BL - OFF_BH));
#pragma unroll
                for (int mt = 0; mt < 2; ++mt) {
                    MMA_BF16(acc[mt][2 * nt2],     aH[mt], bH[0], bH[1]);
                    MMA_BF16(acc[mt][2 * nt2],     aH[mt], bL[0], bL[1]);
                    MMA_BF16(acc[mt][2 * nt2],     aL[mt], bH[0], bH[1]);
                    MMA_BF16(acc[mt][2 * nt2 + 1], aH[mt], bH[2], bH[3]);
                    MMA_BF16(acc[mt][2 * nt2 + 1], aH[mt], bL[2], bL[3]);
                    MMA_BF16(acc[mt][2 * nt2 + 1], aL[mt], bH[2], bH[3]);
                }
            }
        }
        __syncthreads();  // all mma done before hs overwrites A region

        // stage acc -> hs (row stride 68 floats)
#pragma unroll
        for (int mt = 0; mt < 2; ++mt) {
            int rbase = wid * 32 + mt * 16 + row0;
#pragma unroll
            for (int nt = 0; nt < 8; ++nt) {
                float* p0 = hs + rbase * 68 + nt * 8 + c0;
                p0[0] = acc[mt][nt][0]; p0[1] = acc[mt][nt][1];
                float* p1 = p0 + 8 * 68;
                p1[0] = acc[mt][nt][2]; p1[1] = acc[mt][nt][3];
            }
        }
        __syncthreads();

        // epilogue: h = hs + px[send] + b1m  (thread owns fixed quad q)
#pragma unroll
        for (int it = 0; it < 16; ++it) {
            int row = (tid >> 4) + it * 16;
            int e = e0 + row;
            if (e < E) {
                int snd = sSend[row];
                float4 p = __ldg((const float4*)g_px + snd * 16 + q);
                float4 hv = *(float4*)&hs[row * 68 + q * 4];
                float h0 = hv.x + p.x + bq.x, h1 = hv.y + p.y + bq.y;
                float h2 = hv.z + p.z + bq.z, h3 = hv.w + p.w + bq.w;
                if (MODE == 0) {
                    s.x += h0; s.y += h1; s.z += h2; s.w += h3;
                    s2.x += h0 * h0; s2.y += h1 * h1; s2.z += h2 * h2; s2.w += h3 * h3;
                } else {
                    float v0 = fmaxf(fmaf(aq.x, h0, cq.x), 0.f);
                    float v1 = fmaxf(fmaf(aq.y, h1, cq.y), 0.f);
                    float v2 = fmaxf(fmaf(aq.z, h2, cq.z), 0.f);
                    float v3 = fmaxf(fmaf(aq.w, h3, cq.w), 0.f);
                    int rec = sRec[row];
                    float* dst = &g_S[rec * 64 + q * 4];
                    asm volatile("red.global.add.v4.f32 [%0], {%1,%2,%3,%4};"
                                 :: "l"(dst), "f"(v0), "f"(v1), "f"(v2), "f"(v3) : "memory");
                    if (q == 0) atomicAdd(&g_cnt[rec], 1.f);
                }
            }
        }
    }

    if (MODE == 0) {
        __syncthreads();
        atomicAdd(&sRed[q * 4 + 0], s.x);  atomicAdd(&sRed[q * 4 + 1], s.y);
        atomicAdd(&sRed[q * 4 + 2], s.z);  atomicAdd(&sRed[q * 4 + 3], s.w);
        atomicAdd(&sRed[64 + q * 4 + 0], s2.x); atomicAdd(&sRed[64 + q * 4 + 1], s2.y);
        atomicAdd(&sRed[64 + q * 4 + 2], s2.z); atomicAdd(&sRed[64 + q * 4 + 3], s2.w);
        __syncthreads();
        if (tid < 64) {
            atomicAdd(&g_sum_m[tid], sRed[tid]);
            atomicAdd(&g_sq_m[tid], sRed[64 + tid]);
        }
    }
}

// ------------------------- BN coefficient kernels --------------------------
__global__ void k_bnm(const float* __restrict__ gamma, const float* __restrict__ beta,
                      float inv) {
    int j = threadIdx.x;
    float mu = g_sum_m[j] * inv;
    float var = g_sq_m[j] * inv - mu * mu;
    float a = gamma[j] * rsqrtf(var + 1e-5f);
    g_am[j] = a; g_cm[j] = beta[j] - mu * a;
}
__global__ void k_bnn(const float* __restrict__ gamma, const float* __restrict__ beta,
                      float inv) {
    int j = threadIdx.x;
    float mu = g_sum_n[j] * inv;
    float var = g_sq_n[j] * inv - mu * mu;
    float a = gamma[j] * rsqrtf(var + 1e-5f);
    g_an[j] = a; g_cn[j] = beta[j] - mu * a;
}

// ---- k_node1: h_n = x@w1n_top + (S/cnt')@Wc + b1n + [cnt>0]*bvec ----------
__global__ __launch_bounds__(128) void k_node1(const float* __restrict__ x,
                                               const float* __restrict__ w1n,
                                               const float* __restrict__ b1n, int N) {
    __shared__ __align__(16) float sAT[32 * RS];
    __shared__ __align__(16) float sW[64 * 64];
    __shared__ float sSum[64], sSq[64];
    const int tid = threadIdx.x, c = tid & 7, r = tid >> 3;
    const int n0 = blockIdx.x * 128;
    if (tid < 64) { sSum[tid] = 0.f; sSq[tid] = 0.f; }

    ull acc[8][4];
#pragma unroll
    for (int i = 0; i < 8; ++i) { acc[i][0] = 0; acc[i][1] = 0; acc[i][2] = 0; acc[i][3] = 0; }

    for (int ph = 0; ph < 2; ++ph) {
        __syncthreads();
        for (int idx = tid; idx < 1024; idx += 128) {
            int k = idx >> 4, cq = idx & 15;
            *(float4*)&sW[k * 64 + cq * 4] = (ph == 0)
                ? *(const float4*)&w1n[k * 64 + cq * 4]
                : *(const float4*)&g_Wc[k * 64 + cq * 4];
        }
        for (int half = 0; half < 2; ++half) {
            __syncthreads();
#pragma unroll
            for (int it = 0; it < 8; ++it) {
                int idx = tid + it * 128, row = idx >> 3, kq = idx & 7, n = n0 + row;
                float4 v = make_float4(0.f, 0.f, 0.f, 0.f);
                if (n < N) {
                    if (ph == 0) {
                        v = *(const float4*)&x[n * 64 + half * 32 + kq * 4];
                    } else {
                        v = *(const float4*)&g_S[n * 64 + half * 32 + kq * 4];
                        float inv = 1.f / fmaxf(g_cnt[n], 1.f);
                        v.x *= inv; v.y *= inv; v.z *= inv; v.w *= inv;
                    }
                }
                stageT(sAT, v, row, kq);
            }
            __syncthreads();
            mm32(sAT, sW + half * 2048, r, c, acc);
        }
    }

    const float4 bb0 = *(const float4*)&b1n[8 * c];
    const float4 bb1 = *(const float4*)&b1n[8 * c + 4];
    const float4 bv0 = *(const float4*)&g_bvec[8 * c];
    const float4 bv1 = *(const float4*)&g_bvec[8 * c + 4];
    float ls[8], lq[8];
#pragma unroll
    for (int j = 0; j < 8; ++j) { ls[j] = 0.f; lq[j] = 0.f; }

#pragma unroll
    for (int i = 0; i < 8; ++i) {
        int n = n0 + 8 * r + i;
        if (n < N) {
            float ind = (g_cnt[n] > 0.f) ? 1.f : 0.f;
            float h[8];
            unpk(acc[i][0], h[0], h[1]); unpk(acc[i][1], h[2], h[3]);
            unpk(acc[i][2], h[4], h[5]); unpk(acc[i][3], h[6], h[7]);
            h[0] += bb0.x + ind * bv0.x; h[1] += bb0.y + ind * bv0.y;
            h[2] += bb0.z + ind * bv0.z; h[3] += bb0.w + ind * bv0.w;
            h[4] += bb1.x + ind * bv1.x; h[5] += bb1.y + ind * bv1.y;
            h[6] += bb1.z + ind * bv1.z; h[7] += bb1.w + ind * bv1.w;
            *(float4*)&g_hn[n * 64 + 8 * c]     = make_float4(h[0], h[1], h[2], h[3]);
            *(float4*)&g_hn[n * 64 + 8 * c + 4] = make_float4(h[4], h[5], h[6], h[7]);
#pragma unroll
            for (int j = 0; j < 8; ++j) { ls[j] += h[j]; lq[j] += h[j] * h[j]; }
        }
    }
#pragma unroll
    for (int j = 0; j < 8; ++j) {
        atomicAdd(&sSum[8 * c + j], ls[j]);
        atomicAdd(&sSq[8 * c + j], lq[j]);
    }
    __syncthreads();
    if (tid < 64) {
        atomicAdd(&g_sum_n[tid], sSum[tid]);
        atomicAdd(&g_sq_n[tid], sSq[tid]);
    }
}

// ---- k_node2: out = relu(bn(h_n)) @ w2n + b2n -----------------------------
__global__ __launch_bounds__(128) void k_node2(const float* __restrict__ w2n,
                                               const float* __restrict__ b2n,
                                               float* __restrict__ out, int N) {
    __shared__ __align__(16) float sAT[32 * RS];
    __shared__ __align__(16) float sW[64 * 64];
    const int tid = threadIdx.x, c = tid & 7, r = tid >> 3;
    const int n0 = blockIdx.x * 128;

    for (int idx = tid; idx < 1024; idx += 128) {
        int k = idx >> 4, cq = idx & 15;
        *(float4*)&sW[k * 64 + cq * 4] = *(const float4*)&w2n[k * 64 + cq * 4];
    }
    ull acc[8][4];
#pragma unroll
    for (int i = 0; i < 8; ++i) { acc[i][0] = 0; acc[i][1] = 0; acc[i][2] = 0; acc[i][3] = 0; }

    for (int half = 0; half < 2; ++half) {
        __syncthreads();
#pragma unroll
        for (int it = 0; it < 8; ++it) {
            int idx = tid + it * 128, row = idx >> 3, kq = idx & 7, n = n0 + row;
            float4 v = make_float4(0.f, 0.f, 0.f, 0.f);
            if (n < N) {
                int kb = half * 32 + kq * 4;
                float4 h = *(const float4*)&g_hn[n * 64 + kb];
                float4 a = *(const float4*)&g_an[kb];
                float4 cc = *(const float4*)&g_cn[kb];
                v.x = fmaxf(fmaf(a.x, h.x, cc.x), 0.f);
                v.y = fmaxf(fmaf(a.y, h.y, cc.y), 0.f);
                v.z = fmaxf(fmaf(a.z, h.z, cc.z), 0.f);
                v.w = fmaxf(fmaf(a.w, h.w, cc.w), 0.f);
            }
            stageT(sAT, v, row, kq);
        }
        __syncthreads();
        mm32(sAT, sW + half * 2048, r, c, acc);
    }
    const float4 bb0 = *(const float4*)&b2n[8 * c];
    const float4 bb1 = *(const float4*)&b2n[8 * c + 4];
#pragma unroll
    for (int i = 0; i < 8; ++i) {
        int n = n0 + 8 * r + i;
        if (n < N) {
            float h[8];
            unpk(acc[i][0], h[0], h[1]); unpk(acc[i][1], h[2], h[3]);
            unpk(acc[i][2], h[4], h[5]); unpk(acc[i][3], h[6], h[7]);
            *(float4*)&out[n * 64 + 8 * c] =
                make_float4(h[0] + bb0.x, h[1] + bb0.y, h[2] + bb0.z, h[3] + bb0.w);
            *(float4*)&out[n * 64 + 8 * c + 4] =
                make_float4(h[4] + bb1.x, h[5] + bb1.y, h[6] + bb1.z, h[7] + bb1.w);
        }
    }
}

// ------------------------- launch ------------------------------------------
extern "C" void kernel_launch(void* const* d_in, const int* in_sizes, int n_in,
                              void* d_out, int out_size) {
    const float* x       = (const float*)d_in[0];
    const int*   ei      = (const int*)d_in[1];
    const float* ea      = (const float*)d_in[2];
    const float* w1m     = (const float*)d_in[5];
    const float* b1m     = (const float*)d_in[6];
    const float* gamma_m = (const float*)d_in[7];
    const float* beta_m  = (const float*)d_in[8];
    const float* w2m     = (const float*)d_in[9];
    const float* b2m     = (const float*)d_in[10];
    const float* w1n     = (const float*)d_in[11];
    const float* b1n     = (const float*)d_in[12];
    const float* gamma_n = (const float*)d_in[13];
    const float* beta_n  = (const float*)d_in[14];
    const float* w2n     = (const float*)d_in[15];
    const float* b2n     = (const float*)d_in[16];
    float* out = (float*)d_out;

    const int N = in_sizes[0] / 64;
    const int E = in_sizes[2] / 64;
    const int nb = (N + 127) / 128;
    const int ntiles = (E + 255) / 256;
    int grid_e = ntiles < 592 ? ntiles : 592;

    static bool attr_done = false;
    if (!attr_done) {
        cudaFuncSetAttribute(k_edge<0>, cudaFuncAttributeMaxDynamicSharedMemorySize, SMEM_E);
        cudaFuncSetAttribute(k_edge<1>, cudaFuncAttributeMaxDynamicSharedMemorySize, SMEM_E);
        attr_done = true;
    }

    k_zero<<<(N * 16 + 255) / 256, 256>>>(N);
    k_wc<<<1, 256>>>(w2m, w1n, b2m);
    k_px<<<nb, 128>>>(x, w1m, N);
    k_edge<0><<<grid_e, 256, SMEM_E>>>(ea, ei, w1m, b1m, E, ntiles);
    k_bnm<<<1, 64>>>(gamma_m, beta_m, 1.f / (float)E);
    k_edge<1><<<grid_e, 256, SMEM_E>>>(ea, ei, w1m, b1m, E, ntiles);
    k_node1<<<nb, 128>>>(x, w1n, b1n, N);
    k_bnn<<<1, 64>>>(gamma_n, beta_n, 1.f / (float)N);
    k_node2<<<nb, 128>>>(w2n, b2n, out, N);
}

// round 5
// speedup vs baseline: 1.5931x; 1.4698x over previous
#include <cuda_runtime.h>
#include <cuda_bf16.h>
#include <cuda_fp16.h>
#include <cstdint>

#define NMAX 50000
#define EMAX 800000
#define RS 132  // FFMA2 tile row stride (128 + 4 pad)

typedef unsigned long long ull;

// ------------------------- static device scratch ---------------------------
__device__ __align__(16) float  g_px[NMAX * 64];          // x @ w1m_top
__device__ __align__(16) __half g_h16[(size_t)EMAX * 64]; // edge pre-BN acts (fp16)
__device__ __align__(16) float  g_hn[NMAX * 64];          // node pre-BN acts
__device__ __align__(16) float  g_S[NMAX * 64];           // scattered relu sums
__device__ float  g_cnt[NMAX];
__device__ float  g_sum_m[64], g_sq_m[64], g_sum_n[64], g_sq_n[64];
__device__ __align__(16) float g_am[64], g_cm[64], g_an[64], g_cn[64];
__device__ __align__(16) float g_Wc[64 * 64];             // w2m @ w1n_bot
__device__ __align__(16) float g_bvec[64];                // b2m @ w1n_bot

// ------------------------- f32x2 packed FMA helpers ------------------------
__device__ __forceinline__ ull pk2(float x) {
    ull r; asm("mov.b64 %0, {%1, %1};" : "=l"(r) : "f"(x)); return r;
}
__device__ __forceinline__ void fma2(ull& d, ull a, ull b) {
    asm("fma.rn.f32x2 %0, %1, %2, %0;" : "+l"(d) : "l"(a), "l"(b));
}
__device__ __forceinline__ void unpk(ull v, float& lo, float& hi) {
    asm("mov.b64 {%0, %1}, %2;" : "=f"(lo), "=f"(hi) : "l"(v));
}

// ------------------------- mma.sync helpers --------------------------------
__device__ __forceinline__ uint32_t smem_u32(const void* p) {
    uint32_t a;
    asm("{ .reg .u64 t; cvta.to.shared.u64 t, %1; cvt.u32.u64 %0, t; }"
        : "=r"(a) : "l"(p));
    return a;
}

#define LDSM4(R, ADDR) \
    asm volatile("ldmatrix.sync.aligned.m8n8.x4.shared.b16 {%0,%1,%2,%3}, [%4];" \
        : "=r"((R)[0]), "=r"((R)[1]), "=r"((R)[2]), "=r"((R)[3]) : "r"(ADDR))

#define MMA_F16(D, A, B0, B1) \
    asm volatile("mma.sync.aligned.m16n8k16.row.col.f32.f16.f16.f32 " \
        "{%0,%1,%2,%3}, {%4,%5,%6,%7}, {%8,%9}, {%0,%1,%2,%3};" \
        : "+f"((D)[0]), "+f"((D)[1]), "+f"((D)[2]), "+f"((D)[3]) \
        : "r"((A)[0]), "r"((A)[1]), "r"((A)[2]), "r"((A)[3]), "r"(B0), "r"(B1))

// smem layout for k_edgeA (dynamic): total 47616 B (< 48KB default limit)
// fp16 tiles use row stride 72 halves = 144 B (ldmatrix conflict-free).
#define OFF_B    0        // 64 x 72 fp16 = 9216
#define OFF_SEND 9216     // int[256]   = 1024
#define OFF_RED  10240    // float[128] = 512
#define OFF_AH   10752    // 256 x 72 fp16 = 36864 (ends 47616)
#define OFF_HS   10752    // reused after MMA: 256 x 72 fp16 staging
#define SMEM_EA  47616

// ------------------------- FFMA2 GEMM tile core (node kernels) -------------
__device__ __forceinline__ void stageT(float* sAT, float4 v, int row, int kq) {
    sAT[(4 * kq + 0) * RS + row] = v.x;
    sAT[(4 * kq + 1) * RS + row] = v.y;
    sAT[(4 * kq + 2) * RS + row] = v.z;
    sAT[(4 * kq + 3) * RS + row] = v.w;
}
__device__ __forceinline__ void mm32(const float* sAT, const float* sW,
                                     int r, int c, ull acc[8][4]) {
#pragma unroll 4
    for (int k = 0; k < 32; ++k) {
        const float4 A0 = *(const float4*)(sAT + k * RS + 8 * r);
        const float4 A1 = *(const float4*)(sAT + k * RS + 8 * r + 4);
        const ulonglong2 Bv0 = *(const ulonglong2*)(sW + k * 64 + 8 * c);
        const ulonglong2 Bv1 = *(const ulonglong2*)(sW + k * 64 + 8 * c + 4);
        float av[8] = {A0.x, A0.y, A0.z, A0.w, A1.x, A1.y, A1.z, A1.w};
#pragma unroll
        for (int i = 0; i < 8; ++i) {
            ull Ad = pk2(av[i]);
            fma2(acc[i][0], Ad, Bv0.x);
            fma2(acc[i][1], Ad, Bv0.y);
            fma2(acc[i][2], Ad, Bv1.x);
            fma2(acc[i][3], Ad, Bv1.y);
        }
    }
}

// ------------------------- k_zero ------------------------------------------
__global__ void k_zero(int N) {
    int i = blockIdx.x * blockDim.x + threadIdx.x;
    if (i < N * 16) ((float4*)g_S)[i] = make_float4(0.f, 0.f, 0.f, 0.f);
    if (i < N) g_cnt[i] = 0.f;
    if (i < 64) { g_sum_m[i] = 0.f; g_sq_m[i] = 0.f; g_sum_n[i] = 0.f; g_sq_n[i] = 0.f; }
}

// ------------------------- k_wc: Wc = w2m @ w1n_bot ------------------------
__global__ void k_wc(const float* __restrict__ w2m, const float* __restrict__ w1n,
                     const float* __restrict__ b2m) {
    __shared__ __align__(16) float sB[64 * 64];
    int tid = threadIdx.x;
    for (int idx = tid; idx < 1024; idx += 256) {
        int k = idx >> 4, cq = idx & 15;
        *(float4*)&sB[k * 64 + cq * 4] = *(const float4*)&w1n[(64 + k) * 64 + cq * 4];
    }
    __syncthreads();
    for (int idx = tid; idx < 4096; idx += 256) {
        int i = idx >> 6, j = idx & 63;
        float s = 0.f;
#pragma unroll 8
        for (int k = 0; k < 64; ++k) s += w2m[i * 64 + k] * sB[k * 64 + j];
        g_Wc[idx] = s;
    }
    if (tid < 64) {
        float s = 0.f;
#pragma unroll 8
        for (int k = 0; k < 64; ++k) s += b2m[k] * sB[k * 64 + tid];
        g_bvec[tid] = s;
    }
}

// ------------------------- k_px: px = x @ w1m_top --------------------------
__global__ __launch_bounds__(128) void k_px(const float* __restrict__ x,
                                            const float* __restrict__ w1m, int N) {
    __shared__ __align__(16) float sAT[32 * RS];
    __shared__ __align__(16) float sW[64 * 64];
    const int tid = threadIdx.x, c = tid & 7, r = tid >> 3;
    const int n0 = blockIdx.x * 128;

    for (int idx = tid; idx < 1024; idx += 128) {
        int k = idx >> 4, cq = idx & 15;
        *(float4*)&sW[k * 64 + cq * 4] = *(const float4*)&w1m[k * 64 + cq * 4];
    }
    ull acc[8][4];
#pragma unroll
    for (int i = 0; i < 8; ++i) { acc[i][0] = 0; acc[i][1] = 0; acc[i][2] = 0; acc[i][3] = 0; }

    for (int half = 0; half < 2; ++half) {
        __syncthreads();
#pragma unroll
        for (int it = 0; it < 8; ++it) {
            int idx = tid + it * 128, row = idx >> 3, kq = idx & 7, n = n0 + row;
            float4 v = make_float4(0.f, 0.f, 0.f, 0.f);
            if (n < N) v = *(const float4*)&x[n * 64 + half * 32 + kq * 4];
            stageT(sAT, v, row, kq);
        }
        __syncthreads();
        mm32(sAT, sW + half * 2048, r, c, acc);
    }
#pragma unroll
    for (int i = 0; i < 8; ++i) {
        int n = n0 + 8 * r + i;
        if (n < N) {
            float h[8];
            unpk(acc[i][0], h[0], h[1]); unpk(acc[i][1], h[2], h[3]);
            unpk(acc[i][2], h[4], h[5]); unpk(acc[i][3], h[6], h[7]);
            *(float4*)&g_px[n * 64 + 8 * c]     = make_float4(h[0], h[1], h[2], h[3]);
            *(float4*)&g_px[n * 64 + 8 * c + 4] = make_float4(h[4], h[5], h[6], h[7]);
        }
    }
}

// ---- k_edgeA: fp16 HMMA GEMM + px gather; writes h (fp16) + BN stats ------
__global__ __launch_bounds__(256, 3) void k_edgeA(const float* __restrict__ ea,
                                                  const int* __restrict__ ei,
                                                  const float* __restrict__ w1m,
                                                  const float* __restrict__ b1m,
                                                  int E, int ntiles) {
    extern __shared__ __align__(1024) char smem[];
    const uint32_t sb = smem_u32(smem);
    const int tid = threadIdx.x, wid = tid >> 5, lane = tid & 31;
    int* sSend = (int*)(smem + OFF_SEND);
    float* sRed = (float*)(smem + OFF_RED);

    // stage B fp16: B[n][k] = w1m[64+k][n], stride 72 halves — once
    for (int idx = tid; idx < 1024; idx += 256) {
        int n = idx & 63, k4 = (idx >> 6) * 4;
        __half2 h01 = __floats2half2_rn(w1m[4096 + (k4 + 0) * 64 + n],
                                        w1m[4096 + (k4 + 1) * 64 + n]);
        __half2 h23 = __floats2half2_rn(w1m[4096 + (k4 + 2) * 64 + n],
                                        w1m[4096 + (k4 + 3) * 64 + n]);
        *(__half2*)(smem + OFF_B + n * 144 + k4 * 2 + 0) = h01;
        *(__half2*)(smem + OFF_B + n * 144 + k4 * 2 + 4) = h23;
    }
    if (tid < 128) sRed[tid] = 0.f;

    const int q = tid & 15;
    const float4 bq = __ldg((const float4*)b1m + q);
    float4 s  = make_float4(0.f, 0.f, 0.f, 0.f);
    float4 s2 = make_float4(0.f, 0.f, 0.f, 0.f);

    // ldmatrix fragment addresses
    const int r8 = lane & 7, sel = lane >> 3;
    const uint32_t aBase = sb + (uint32_t)((wid * 32 + r8 + (sel & 1) * 8) * 144
                                           + ((sel >> 1) * 8) * 2);
    const uint32_t bBase = sb + (uint32_t)((((sel >> 1) * 8) + r8) * 144
                                           + ((sel & 1) * 8) * 2);
    const int row0 = lane >> 2, c0 = (lane & 3) * 2;

    for (int t = blockIdx.x; t < ntiles; t += gridDim.x) {
        const int e0 = t * 256;
        __syncthreads();  // guard smem reuse across tiles
        { int e = e0 + tid; sSend[tid] = (e < E) ? ei[e] : 0; }

        // stage A fp16 (zero-padded)
#pragma unroll
        for (int it = 0; it < 16; ++it) {
            int idx = tid + it * 256, row = idx >> 4, kq = idx & 15;
            float4 v = make_float4(0.f, 0.f, 0.f, 0.f);
            if (e0 + row < E) v = *(const float4*)&ea[(size_t)(e0 + row) * 64 + kq * 4];
            *(__half2*)(smem + OFF_AH + row * 144 + kq * 8 + 0) = __floats2half2_rn(v.x, v.y);
            *(__half2*)(smem + OFF_AH + row * 144 + kq * 8 + 4) = __floats2half2_rn(v.z, v.w);
        }
        __syncthreads();

        // MMA: D = A @ B  (fp16 in, fp32 acc)
        float acc[2][8][4];
#pragma unroll
        for (int mt = 0; mt < 2; ++mt)
#pragma unroll
            for (int nt = 0; nt < 8; ++nt)
#pragma unroll
                for (int j = 0; j < 4; ++j) acc[mt][nt][j] = 0.f;

#pragma unroll
        for (int kt = 0; kt < 4; ++kt) {
            uint32_t aF[2][4];
            LDSM4(aF[0], aBase + OFF_AH + kt * 32);
            LDSM4(aF[1], aBase + OFF_AH + 2304 + kt * 32);
#pragma unroll
            for (int nt2 = 0; nt2 < 4; ++nt2) {
                uint32_t bF[4];
                LDSM4(bF, bBase + OFF_B + nt2 * 2304 + kt * 32);
#pragma unroll
                for (int mt = 0; mt < 2; ++mt) {
                    MMA_F16(acc[mt][2 * nt2],     aF[mt], bF[0], bF[1]);
                    MMA_F16(acc[mt][2 * nt2 + 1], aF[mt], bF[2], bF[3]);
                }
            }
        }
        __syncthreads();  // A tile dead -> HS may overwrite

        // stage acc as fp16 into HS (same region as AH, stride 72 halves)
#pragma unroll
        for (int mt = 0; mt < 2; ++mt) {
            int rbase = wid * 32 + mt * 16 + row0;
#pragma unroll
            for (int nt = 0; nt < 8; ++nt) {
                *(__half2*)(smem + OFF_HS + rbase * 144 + (8 * nt + c0) * 2) =
                    __floats2half2_rn(acc[mt][nt][0], acc[mt][nt][1]);
                *(__half2*)(smem + OFF_HS + (rbase + 8) * 144 + (8 * nt + c0) * 2) =
                    __floats2half2_rn(acc[mt][nt][2], acc[mt][nt][3]);
            }
        }
        __syncthreads();

        // epilogue: h = gemm + px[send] + b1m ; write fp16 h ; stats
#pragma unroll
        for (int it = 0; it < 16; ++it) {
            int row = (tid >> 4) + it * 16;
            int e = e0 + row;
            if (e < E) {
                int snd = sSend[row];
                float4 p = __ldg((const float4*)g_px + snd * 16 + q);
                __half2 g01 = *(__half2*)(smem + OFF_HS + row * 144 + q * 8 + 0);
                __half2 g23 = *(__half2*)(smem + OFF_HS + row * 144 + q * 8 + 4);
                float2 f01 = __half22float2(g01), f23 = __half22float2(g23);
                float h0 = f01.x + p.x + bq.x, h1 = f01.y + p.y + bq.y;
                float h2 = f23.x + p.z + bq.z, h3 = f23.y + p.w + bq.w;
                s.x += h0; s.y += h1; s.z += h2; s.w += h3;
                s2.x += h0 * h0; s2.y += h1 * h1; s2.z += h2 * h2; s2.w += h3 * h3;
                __half2* dst = (__half2*)&g_h16[(size_t)e * 64 + q * 4];
                dst[0] = __floats2half2_rn(h0, h1);
                dst[1] = __floats2half2_rn(h2, h3);
            }
        }
    }

    // flush BN stats
    __syncthreads();
    atomicAdd(&sRed[q * 4 + 0], s.x);  atomicAdd(&sRed[q * 4 + 1], s.y);
    atomicAdd(&sRed[q * 4 + 2], s.z);  atomicAdd(&sRed[q * 4 + 3], s.w);
    atomicAdd(&sRed[64 + q * 4 + 0], s2.x); atomicAdd(&sRed[64 + q * 4 + 1], s2.y);
    atomicAdd(&sRed[64 + q * 4 + 2], s2.z); atomicAdd(&sRed[64 + q * 4 + 3], s2.w);
    __syncthreads();
    if (tid < 64) {
        atomicAdd(&g_sum_m[tid], sRed[tid]);
        atomicAdd(&g_sq_m[tid], sRed[64 + tid]);
    }
}

// ------------------------- BN coefficient kernels --------------------------
__global__ void k_bnm(const float* __restrict__ gamma, const float* __restrict__ beta,
                      float inv) {
    int j = threadIdx.x;
    float mu = g_sum_m[j] * inv;
    float var = g_sq_m[j] * inv - mu * mu;
    float a = gamma[j] * rsqrtf(var + 1e-5f);
    g_am[j] = a; g_cm[j] = beta[j] - mu * a;
}
__global__ void k_bnn(const float* __restrict__ gamma, const float* __restrict__ beta,
                      float inv) {
    int j = threadIdx.x;
    float mu = g_sum_n[j] * inv;
    float var = g_sq_n[j] * inv - mu * mu;
    float a = gamma[j] * rsqrtf(var + 1e-5f);
    g_an[j] = a; g_cn[j] = beta[j] - mu * a;
}

// ---- k_edgeB: relu(bn(h16)) scatter-add into g_S, count into g_cnt --------
__global__ __launch_bounds__(256) void k_edgeB(const int* __restrict__ ei, int E) {
    int idx = blockIdx.x * 256 + threadIdx.x;
    if (idx >= E * 16) return;
    int e = idx >> 4, q = idx & 15;
    const __half2* hp = (const __half2*)&g_h16[(size_t)e * 64 + q * 4];
    float2 f01 = __half22float2(hp[0]);
    float2 f23 = __half22float2(hp[1]);
    float4 a = *(const float4*)&g_am[q * 4];
    float4 c = *(const float4*)&g_cm[q * 4];
    float v0 = fmaxf(fmaf(a.x, f01.x, c.x), 0.f);
    float v1 = fmaxf(fmaf(a.y, f01.y, c.y), 0.f);
    float v2 = fmaxf(fmaf(a.z, f23.x, c.z), 0.f);
    float v3 = fmaxf(fmaf(a.w, f23.y, c.w), 0.f);
    int rec = ei[E + e];
    float* dst = &g_S[rec * 64 + q * 4];
    asm volatile("red.global.add.v4.f32 [%0], {%1,%2,%3,%4};"
                 :: "l"(dst), "f"(v0), "f"(v1), "f"(v2), "f"(v3) : "memory");
    if (q == 0) atomicAdd(&g_cnt[rec], 1.f);
}

// ---- k_node1: h_n = x@w1n_top + (S/cnt')@Wc + b1n + [cnt>0]*bvec ----------
__global__ __launch_bounds__(128) void k_node1(const float* __restrict__ x,
                                               const float* __restrict__ w1n,
                                               const float* __restrict__ b1n, int N) {
    __shared__ __align__(16) float sAT[32 * RS];
    __shared__ __align__(16) float sW[64 * 64];
    __shared__ float sSum[64], sSq[64];
    const int tid = threadIdx.x, c = tid & 7, r = tid >> 3;
    const int n0 = blockIdx.x * 128;
    if (tid < 64) { sSum[tid] = 0.f; sSq[tid] = 0.f; }

    ull acc[8][4];
#pragma unroll
    for (int i = 0; i < 8; ++i) { acc[i][0] = 0; acc[i][1] = 0; acc[i][2] = 0; acc[i][3] = 0; }

    for (int ph = 0; ph < 2; ++ph) {
        __syncthreads();
        for (int idx = tid; idx < 1024; idx += 128) {
            int k = idx >> 4, cq = idx & 15;
            *(float4*)&sW[k * 64 + cq * 4] = (ph == 0)
                ? *(const float4*)&w1n[k * 64 + cq * 4]
                : *(const float4*)&g_Wc[k * 64 + cq * 4];
        }
        for (int half = 0; half < 2; ++half) {
            __syncthreads();
#pragma unroll
            for (int it = 0; it < 8; ++it) {
                int idx = tid + it * 128, row = idx >> 3, kq = idx & 7, n = n0 + row;
                float4 v = make_float4(0.f, 0.f, 0.f, 0.f);
                if (n < N) {
                    if (ph == 0) {
                        v = *(const float4*)&x[n * 64 + half * 32 + kq * 4];
                    } else {
                        v = *(const float4*)&g_S[n * 64 + half * 32 + kq * 4];
                        float inv = 1.f / fmaxf(g_cnt[n], 1.f);
                        v.x *= inv; v.y *= inv; v.z *= inv; v.w *= inv;
                    }
                }
                stageT(sAT, v, row, kq);
            }
            __syncthreads();
            mm32(sAT, sW + half * 2048, r, c, acc);
        }
    }

    const float4 bb0 = *(const float4*)&b1n[8 * c];
    const float4 bb1 = *(const float4*)&b1n[8 * c + 4];
    const float4 bv0 = *(const float4*)&g_bvec[8 * c];
    const float4 bv1 = *(const float4*)&g_bvec[8 * c + 4];
    float ls[8], lq[8];
#pragma unroll
    for (int j = 0; j < 8; ++j) { ls[j] = 0.f; lq[j] = 0.f; }

#pragma unroll
    for (int i = 0; i < 8; ++i) {
        int n = n0 + 8 * r + i;
        if (n < N) {
            float ind = (g_cnt[n] > 0.f) ? 1.f : 0.f;
            float h[8];
            unpk(acc[i][0], h[0], h[1]); unpk(acc[i][1], h[2], h[3]);
            unpk(acc[i][2], h[4], h[5]); unpk(acc[i][3], h[6], h[7]);
            h[0] += bb0.x + ind * bv0.x; h[1] += bb0.y + ind * bv0.y;
            h[2] += bb0.z + ind * bv0.z; h[3] += bb0.w + ind * bv0.w;
            h[4] += bb1.x + ind * bv1.x; h[5] += bb1.y + ind * bv1.y;
            h[6] += bb1.z + ind * bv1.z; h[7] += bb1.w + ind * bv1.w;
            *(float4*)&g_hn[n * 64 + 8 * c]     = make_float4(h[0], h[1], h[2], h[3]);
            *(float4*)&g_hn[n * 64 + 8 * c + 4] = make_float4(h[4], h[5], h[6], h[7]);
#pragma unroll
            for (int j = 0; j < 8; ++j) { ls[j] += h[j]; lq[j] += h[j] * h[j]; }
        }
    }
#pragma unroll
    for (int j = 0; j < 8; ++j) {
        atomicAdd(&sSum[8 * c + j], ls[j]);
        atomicAdd(&sSq[8 * c + j], lq[j]);
    }
    __syncthreads();
    if (tid < 64) {
        atomicAdd(&g_sum_n[tid], sSum[tid]);
        atomicAdd(&g_sq_n[tid], sSq[tid]);
    }
}

// ---- k_node2: out = relu(bn(h_n)) @ w2n + b2n -----------------------------
__global__ __launch_bounds__(128) void k_node2(const float* __restrict__ w2n,
                                               const float* __restrict__ b2n,
                                               float* __restrict__ out, int N) {
    __shared__ __align__(16) float sAT[32 * RS];
    __shared__ __align__(16) float sW[64 * 64];
    const int tid = threadIdx.x, c = tid & 7, r = tid >> 3;
    const int n0 = blockIdx.x * 128;

    for (int idx = tid; idx < 1024; idx += 128) {
        int k = idx >> 4, cq = idx & 15;
        *(float4*)&sW[k * 64 + cq * 4] = *(const float4*)&w2n[k * 64 + cq * 4];
    }
    ull acc[8][4];
#pragma unroll
    for (int i = 0; i < 8; ++i) { acc[i][0] = 0; acc[i][1] = 0; acc[i][2] = 0; acc[i][3] = 0; }

    for (int half = 0; half < 2; ++half) {
        __syncthreads();
#pragma unroll
        for (int it = 0; it < 8; ++it) {
            int idx = tid + it * 128, row = idx >> 3, kq = idx & 7, n = n0 + row;
            float4 v = make_float4(0.f, 0.f, 0.f, 0.f);
            if (n < N) {
                int kb = half * 32 + kq * 4;
                float4 h = *(const float4*)&g_hn[n * 64 + kb];
                float4 a = *(const float4*)&g_an[kb];
                float4 cc = *(const float4*)&g_cn[kb];
                v.x = fmaxf(fmaf(a.x, h.x, cc.x), 0.f);
                v.y = fmaxf(fmaf(a.y, h.y, cc.y), 0.f);
                v.z = fmaxf(fmaf(a.z, h.z, cc.z), 0.f);
                v.w = fmaxf(fmaf(a.w, h.w, cc.w), 0.f);
            }
            stageT(sAT, v, row, kq);
        }
        __syncthreads();
        mm32(sAT, sW + half * 2048, r, c, acc);
    }
    const float4 bb0 = *(const float4*)&b2n[8 * c];
    const float4 bb1 = *(const float4*)&b2n[8 * c + 4];
#pragma unroll
    for (int i = 0; i < 8; ++i) {
        int n = n0 + 8 * r + i;
        if (n < N) {
            float h[8];
            unpk(acc[i][0], h[0], h[1]); unpk(acc[i][1], h[2], h[3]);
            unpk(acc[i][2], h[4], h[5]); unpk(acc[i][3], h[6], h[7]);
            *(float4*)&out[n * 64 + 8 * c] =
                make_float4(h[0] + bb0.x, h[1] + bb0.y, h[2] + bb0.z, h[3] + bb0.w);
            *(float4*)&out[n * 64 + 8 * c + 4] =
                make_float4(h[4] + bb1.x, h[5] + bb1.y, h[6] + bb1.z, h[7] + bb1.w);
        }
    }
}

// ------------------------- launch ------------------------------------------
extern "C" void kernel_launch(void* const* d_in, const int* in_sizes, int n_in,
                              void* d_out, int out_size) {
    const float* x       = (const float*)d_in[0];
    const int*   ei      = (const int*)d_in[1];
    const float* ea      = (const float*)d_in[2];
    const float* w1m     = (const float*)d_in[5];
    const float* b1m     = (const float*)d_in[6];
    const float* gamma_m = (const float*)d_in[7];
    const float* beta_m  = (const float*)d_in[8];
    const float* w2m     = (const float*)d_in[9];
    const float* b2m     = (const float*)d_in[10];
    const float* w1n     = (const float*)d_in[11];
    const float* b1n     = (const float*)d_in[12];
    const float* gamma_n = (const float*)d_in[13];
    const float* beta_n  = (const float*)d_in[14];
    const float* w2n     = (const float*)d_in[15];
    const float* b2n     = (const float*)d_in[16];
    float* out = (float*)d_out;

    const int N = in_sizes[0] / 64;
    const int E = in_sizes[2] / 64;
    const int nb = (N + 127) / 128;
    const int ntiles = (E + 255) / 256;
    const int grid_e = ntiles < 444 ? ntiles : 444;

    k_zero<<<(N * 16 + 255) / 256, 256>>>(N);
    k_wc<<<1, 256>>>(w2m, w1n, b2m);
    k_px<<<nb, 128>>>(x, w1m, N);
    k_edgeA<<<grid_e, 256, SMEM_EA>>>(ea, ei, w1m, b1m, E, ntiles);
    k_bnm<<<1, 64>>>(gamma_m, beta_m, 1.f / (float)E);
    k_edgeB<<<(E * 16 + 255) / 256, 256>>>(ei, E);
    k_node1<<<nb, 128>>>(x, w1n, b1n, N);
    k_bnn<<<1, 64>>>(gamma_n, beta_n, 1.f / (float)N);
    k_node2<<<nb, 128>>>(w2n, b2n, out, N);
}